// round 12
// baseline (speedup 1.0000x reference)
#include <cuda_runtime.h>
#include <cuda_fp16.h>
#include <cstdint>

// Problem constants (shapes are fixed by the dataset).
#define NN 100000
#define EE 1600000
#define HD 64
#define SCAN_CHUNK 1024
#define MAX_SCAN_BLOCKS 128
#define GROWS 64    // GEMM rows per block
#define STAGE 8     // cp.async pipeline depth per warp (power of 2)

// ---------------- scratch (device globals: allocation-free) ----------------
__device__ int    g_is64;
__device__ int    g_cnt[NN];
__device__ int    g_rowstart[NN + 1];
__device__ int    g_cursor[NN];
__device__ float  g_dis[NN];
__device__ int    g_blocksum[MAX_SCAN_BLOCKS];
__device__ int    g_blockoff[MAX_SCAN_BLOCKS];
__device__ __align__(128) int2   g_epack[EE];               // packed (src, weight-bits)
__device__ __align__(128) __half g_bufAh[(size_t)NN * HD];  // fp16 GEMM out (gather in)
__device__ __align__(128) float  g_bufB[(size_t)NN * HD];   // fp32 gather out (GEMM in)

// ---------------- dtype sniff: int64 edge_index has zero high words ----------------
__global__ void k_detect(const void* ei) {
    __shared__ int nz;
    if (threadIdx.x == 0) nz = 0;
    __syncthreads();
    unsigned v = ((const unsigned*)ei)[2 * threadIdx.x + 1];
    if (v != 0) atomicOr(&nz, 1);
    __syncthreads();
    if (threadIdx.x == 0) g_is64 = (nz == 0) ? 1 : 0;
}

__global__ void k_zero_int(int* p, int n) {
    int i = blockIdx.x * blockDim.x + threadIdx.x;
    if (i < n) p[i] = 0;
}

// ---------------- histogram dst directly from edge_index ----------------
__global__ void k_hist(const void* ei, int e, int n, int* __restrict__ cnt) {
    int i = blockIdx.x * blockDim.x + threadIdx.x;
    if (i >= e) return;
    int d = g_is64 ? (int)((const long long*)ei)[(size_t)e + i]
                   : ((const int*)ei)[e + i];
    if ((unsigned)d < (unsigned)n) atomicAdd(&cnt[d], 1);
}

// ---------------- 3-phase parallel scan over cnt ----------------
__global__ void __launch_bounds__(SCAN_CHUNK) k_scan1(const int* __restrict__ cnt,
                                                      int* __restrict__ rowstart,
                                                      int* __restrict__ blocksum,
                                                      float* __restrict__ dis, int n) {
    __shared__ int sh[SCAN_CHUNK];
    int t = threadIdx.x;
    int i = blockIdx.x * SCAN_CHUNK + t;
    int v = (i < n) ? cnt[i] : 0;
    if (i < n) dis[i] = rsqrtf((float)v + 1.0f);
    sh[t] = v;
    __syncthreads();
    #pragma unroll
    for (int off = 1; off < SCAN_CHUNK; off <<= 1) {
        int add = (t >= off) ? sh[t - off] : 0;
        __syncthreads();
        sh[t] += add;
        __syncthreads();
    }
    if (i < n) rowstart[i] = sh[t] - v;
    if (t == SCAN_CHUNK - 1) blocksum[blockIdx.x] = sh[SCAN_CHUNK - 1];
}

__global__ void k_scan2(const int* __restrict__ blocksum, int* __restrict__ blockoff,
                        int nb, int* __restrict__ rowstart, int n) {
    __shared__ int sh[MAX_SCAN_BLOCKS];
    int t = threadIdx.x;
    int v = (t < nb) ? blocksum[t] : 0;
    sh[t] = v;
    __syncthreads();
    #pragma unroll
    for (int off = 1; off < MAX_SCAN_BLOCKS; off <<= 1) {
        int add = (t >= off) ? sh[t - off] : 0;
        __syncthreads();
        sh[t] += add;
        __syncthreads();
    }
    if (t < nb) blockoff[t] = sh[t] - v;
    if (t == MAX_SCAN_BLOCKS - 1) rowstart[n] = sh[MAX_SCAN_BLOCKS - 1];
}

__global__ void __launch_bounds__(SCAN_CHUNK) k_scan3(int* __restrict__ rowstart,
                                                      int* __restrict__ cursor,
                                                      const int* __restrict__ blockoff, int n) {
    int i = blockIdx.x * SCAN_CHUNK + threadIdx.x;
    if (i < n) {
        int r = rowstart[i] + blockoff[blockIdx.x];
        rowstart[i] = r;
        cursor[i]   = r;
    }
}

// ---------------- CSR fill: read edge_index directly, one packed STG.64 per edge ----------------
__global__ void k_fill(const void* ei, int e, int n, const float* __restrict__ dis,
                       int* __restrict__ cursor, int2* __restrict__ epack) {
    int i = blockIdx.x * blockDim.x + threadIdx.x;
    if (i >= e) return;
    int s, d;
    if (g_is64) {
        const long long* p = (const long long*)ei;
        s = (int)p[i];
        d = (int)p[(size_t)e + i];
    } else {
        const int* p = (const int*)ei;
        s = p[i];
        d = p[e + i];
    }
    if ((unsigned)s >= (unsigned)n || (unsigned)d >= (unsigned)n) return;
    float w = dis[s] * dis[d];
    int p = atomicAdd(&cursor[d], 1);
    epack[p] = make_int2(s, __float_as_int(w));
}

// ---------------- tf32 helpers ----------------
__device__ __forceinline__ float to_tf32(float x) {
    unsigned r;
    asm("cvt.rna.tf32.f32 %0, %1;" : "=r"(r) : "f"(x));
    return __uint_as_float(r);
}

__device__ __forceinline__ void mma_tf32(float* c, unsigned a0, unsigned a1,
                                         unsigned a2, unsigned a3,
                                         unsigned b0, unsigned b1) {
    asm volatile(
        "mma.sync.aligned.m16n8k8.row.col.f32.tf32.tf32.f32 "
        "{%0,%1,%2,%3}, {%4,%5,%6,%7}, {%8,%9}, {%0,%1,%2,%3};"
        : "+f"(c[0]), "+f"(c[1]), "+f"(c[2]), "+f"(c[3])
        : "r"(a0), "r"(a1), "r"(a2), "r"(a3), "r"(b0), "r"(b1));
}

// ---------------- GEMM (tf32 tensor core): Yh[n,64] = act(X)[n,64] @ W[64,64] ----------------
__global__ void __launch_bounds__(128) k_gemm_tc(const float* __restrict__ X,
                                                 const float* __restrict__ W,
                                                 __half* __restrict__ Y, int n, int relu_in) {
    __shared__ float sA[GROWS * 68];
    __shared__ float sB[64 * 68];

    int t    = threadIdx.x;
    int row0 = blockIdx.x * GROWS;

    #pragma unroll
    for (int i = 0; i < 8; i++) {
        int idx = i * 512 + t * 4;
        float4 v = *(const float4*)&W[idx];
        int k  = idx >> 6;
        int nn = idx & 63;
        sB[k * 68 + nn + 0] = to_tf32(v.x);
        sB[k * 68 + nn + 1] = to_tf32(v.y);
        sB[k * 68 + nn + 2] = to_tf32(v.z);
        sB[k * 68 + nn + 3] = to_tf32(v.w);
    }
    {
        int kc = (t & 15) * 4;
        int rl = t >> 4;
        #pragma unroll
        for (int i = 0; i < 8; i++) {
            int r  = rl + i * 8;
            int gr = row0 + r;
            float4 v = make_float4(0.f, 0.f, 0.f, 0.f);
            if (gr < n) v = *(const float4*)&X[(size_t)gr * HD + kc];
            if (relu_in) {
                v.x = fmaxf(v.x, 0.f); v.y = fmaxf(v.y, 0.f);
                v.z = fmaxf(v.z, 0.f); v.w = fmaxf(v.w, 0.f);
            }
            sA[r * 68 + kc + 0] = to_tf32(v.x);
            sA[r * 68 + kc + 1] = to_tf32(v.y);
            sA[r * 68 + kc + 2] = to_tf32(v.z);
            sA[r * 68 + kc + 3] = to_tf32(v.w);
        }
    }
    __syncthreads();

    int warp = t >> 5, lane = t & 31;
    int g  = lane >> 2;
    int tq = lane & 3;
    int mrow = warp * 16;

    float c[8][4];
    #pragma unroll
    for (int nf = 0; nf < 8; nf++)
        #pragma unroll
        for (int j = 0; j < 4; j++) c[nf][j] = 0.f;

    #pragma unroll
    for (int kk = 0; kk < 8; kk++) {
        int k0 = kk * 8;
        unsigned a0 = __float_as_uint(sA[(mrow + g)     * 68 + k0 + tq]);
        unsigned a1 = __float_as_uint(sA[(mrow + g + 8) * 68 + k0 + tq]);
        unsigned a2 = __float_as_uint(sA[(mrow + g)     * 68 + k0 + tq + 4]);
        unsigned a3 = __float_as_uint(sA[(mrow + g + 8) * 68 + k0 + tq + 4]);
        #pragma unroll
        for (int nf = 0; nf < 8; nf++) {
            unsigned b0 = __float_as_uint(sB[(k0 + tq)     * 68 + nf * 8 + g]);
            unsigned b1 = __float_as_uint(sB[(k0 + tq + 4) * 68 + nf * 8 + g]);
            mma_tf32(c[nf], a0, a1, a2, a3, b0, b1);
        }
    }

    int gr0 = row0 + mrow + g;
    int gr1 = gr0 + 8;
    #pragma unroll
    for (int nf = 0; nf < 8; nf++) {
        int colb = nf * 8 + 2 * tq;
        if (gr0 < n) {
            __half2 h = __floats2half2_rn(c[nf][0], c[nf][1]);
            *(__half2*)&Y[(size_t)gr0 * HD + colb] = h;
        }
        if (gr1 < n) {
            __half2 h = __floats2half2_rn(c[nf][2], c[nf][3]);
            *(__half2*)&Y[(size_t)gr1 * HD + colb] = h;
        }
    }
}

// ---------------- Gather: one warp per node, cp.async-staged rows ----------------
// LDGSTS has no outstanding-line cap like register LDG: STAGE rows in flight per warp.
// Y[i] = sum_{e in CSR(i)} A[src_e]*w_e  +  A[i]*dis[i]^2  +  b   (fp32 accumulate)
__global__ void __launch_bounds__(256) k_gather(const __half* __restrict__ A,
                                                const int* __restrict__ rowstart,
                                                const int2* __restrict__ epack,
                                                const float* __restrict__ dis,
                                                const float* __restrict__ bias,
                                                float* __restrict__ Y, int n) {
    __shared__ __align__(16) char sbuf[8][STAGE][128];   // 8 warps x STAGE x 128B row
    __shared__ float sw[8][STAGE];

    int wib  = threadIdx.x >> 5;   // warp in block
    int wid  = (blockIdx.x * blockDim.x + threadIdx.x) >> 5;
    int lane = threadIdx.x & 31;
    if (wid >= n) return;          // whole warp exits together

    // Self-loop term: every lane owns 2 fp16 channels.
    float d  = dis[wid];
    float sn = d * d;
    float2 acc;
    {
        __half2 a = *(const __half2*)&A[(size_t)wid * HD + lane * 2];
        float2 f = __half22float2(a);
        acc.x = f.x * sn;
        acc.y = f.y * sn;
    }

    int e0  = rowstart[wid];
    int deg = rowstart[wid + 1] - e0;

    char (*buf)[128] = sbuf[wib];
    float* ws = sw[wib];

    // Prologue: always commit exactly STAGE groups (empty groups complete immediately),
    // so group #j always corresponds to edge j.
    #pragma unroll
    for (int k = 0; k < STAGE; k++) {
        if (k < deg) {
            int2 p = epack[e0 + k];
            if (lane == 0) ws[k] = __int_as_float(p.y);
            if (lane < 8) {
                const char* gptr = (const char*)&A[(size_t)p.x * HD] + lane * 16;
                unsigned saddr = (unsigned)__cvta_generic_to_shared(&buf[k][lane * 16]);
                asm volatile("cp.async.ca.shared.global [%0], [%1], 16;\n"
                             :: "r"(saddr), "l"(gptr));
            }
        }
        asm volatile("cp.async.commit_group;\n");
    }

    for (int j = 0; j < deg; j++) {
        int slot = j & (STAGE - 1);
        asm volatile("cp.async.wait_group %0;\n" :: "n"(STAGE - 1));
        __syncwarp();                               // data visible to all lanes
        float  w = ws[slot];
        __half2 h = *(__half2*)&buf[slot][lane * 4];
        float2 f = __half22float2(h);
        acc.x = fmaf(f.x, w, acc.x);
        acc.y = fmaf(f.y, w, acc.y);
        __syncwarp();                               // all lanes done before slot reuse

        int k = j + STAGE;
        if (k < deg) {
            int2 p = epack[e0 + k];
            if (lane == 0) ws[slot] = __int_as_float(p.y);
            if (lane < 8) {
                const char* gptr = (const char*)&A[(size_t)p.x * HD] + lane * 16;
                unsigned saddr = (unsigned)__cvta_generic_to_shared(&buf[slot][lane * 16]);
                asm volatile("cp.async.ca.shared.global [%0], [%1], 16;\n"
                             :: "r"(saddr), "l"(gptr));
            }
        }
        asm volatile("cp.async.commit_group;\n");
    }
    asm volatile("cp.async.wait_group 0;\n");

    float2 b = *(const float2*)&bias[lane * 2];
    acc.x += b.x;
    acc.y += b.y;
    *(float2*)&Y[(size_t)wid * HD + lane * 2] = acc;
}

// ---------------- launch ----------------
extern "C" void kernel_launch(void* const* d_in, const int* in_sizes, int n_in,
                              void* d_out, int out_size) {
    const float* x  = (const float*)d_in[0];
    const void*  ei = d_in[1];   // [2,E]; dtype sniffed on device (int32 vs int64)
    const float* W1 = (const float*)d_in[3];
    const float* b1 = (const float*)d_in[4];
    const float* W2 = (const float*)d_in[5];
    const float* b2 = (const float*)d_in[6];
    const float* W3 = (const float*)d_in[7];
    const float* b3 = (const float*)d_in[8];

    int n = in_sizes[0] / HD;   // 100000
    int e = in_sizes[1] / 2;    // 1600000

    int*    cnt;      cudaGetSymbolAddress((void**)&cnt, g_cnt);
    int*    rowstart; cudaGetSymbolAddress((void**)&rowstart, g_rowstart);
    int*    cursor;   cudaGetSymbolAddress((void**)&cursor, g_cursor);
    float*  dis;      cudaGetSymbolAddress((void**)&dis, g_dis);
    int*    blocksum; cudaGetSymbolAddress((void**)&blocksum, g_blocksum);
    int*    blockoff; cudaGetSymbolAddress((void**)&blockoff, g_blockoff);
    int2*   epack;    cudaGetSymbolAddress((void**)&epack, g_epack);
    __half* bufAh;    cudaGetSymbolAddress((void**)&bufAh, g_bufAh);
    float*  bufB;     cudaGetSymbolAddress((void**)&bufB, g_bufB);
    float*  out = (float*)d_out;

    int nb_n = (n + 255) / 256;
    int nb_e = (e + 255) / 256;
    int nb_g = (n * 32 + 255) / 256;               // one warp per node
    int nb_m = (n + GROWS - 1) / GROWS;            // 64-row GEMM tiles
    int nb_s = (n + SCAN_CHUNK - 1) / SCAN_CHUNK;  // 98 scan blocks

    // ---- CSR build from edge_index (once per call) ----
    k_detect<<<1, 256>>>(ei);
    k_zero_int<<<nb_n, 256>>>(cnt, n);
    k_hist<<<nb_e, 256>>>(ei, e, n, cnt);
    k_scan1<<<nb_s, SCAN_CHUNK>>>(cnt, rowstart, blocksum, dis, n);
    k_scan2<<<1, MAX_SCAN_BLOCKS>>>(blocksum, blockoff, nb_s, rowstart, n);
    k_scan3<<<nb_s, SCAN_CHUNK>>>(rowstart, cursor, blockoff, n);
    k_fill<<<nb_e, 256>>>(ei, e, n, dis, cursor, epack);

    // ---- layer 1 ----
    k_gemm_tc<<<nb_m, 128>>>(x, W1, bufAh, n, 0);
    k_gather<<<nb_g, 256>>>(bufAh, rowstart, epack, dis, b1, bufB, n);
    // ---- layer 2 (ReLU fused into GEMM input load) ----
    k_gemm_tc<<<nb_m, 128>>>(bufB, W2, bufAh, n, 1);
    k_gather<<<nb_g, 256>>>(bufAh, rowstart, epack, dis, b2, bufB, n);
    // ---- layer 3 ----
    k_gemm_tc<<<nb_m, 128>>>(bufB, W3, bufAh, n, 1);
    k_gather<<<nb_g, 256>>>(bufAh, rowstart, epack, dis, b3, out, n);
}

// round 13
// speedup vs baseline: 1.8588x; 1.8588x over previous
#include <cuda_runtime.h>
#include <cuda_fp16.h>
#include <cstdint>

// Problem constants (shapes are fixed by the dataset).
#define NN 100000
#define EE 1600000
#define HD 64
#define SCAN_CHUNK 1024
#define MAX_SCAN_BLOCKS 128
#define GROWS 64    // GEMM rows per block

// ---------------- scratch (device globals: allocation-free) ----------------
__device__ int    g_is64;
__device__ int    g_cnt[NN];
__device__ int    g_rowstart[NN + 1];
__device__ int    g_rank[EE];                               // edge rank within dst bucket
__device__ float  g_dis[NN];
__device__ int    g_blocksum[MAX_SCAN_BLOCKS];
__device__ int    g_blockoff[MAX_SCAN_BLOCKS];
__device__ __align__(128) int2   g_epack[EE];               // packed (src, weight-bits)
__device__ __align__(128) __half g_bufAh[(size_t)NN * HD];  // fp16 GEMM out (gather in)
__device__ __align__(128) float  g_bufB[(size_t)NN * HD];   // fp32 gather out (GEMM in)

// ---------------- dtype sniff: int64 edge_index has zero high words ----------------
__global__ void k_detect(const void* ei) {
    __shared__ int nz;
    if (threadIdx.x == 0) nz = 0;
    __syncthreads();
    unsigned v = ((const unsigned*)ei)[2 * threadIdx.x + 1];
    if (v != 0) atomicOr(&nz, 1);
    __syncthreads();
    if (threadIdx.x == 0) g_is64 = (nz == 0) ? 1 : 0;
}

__global__ void k_zero_int(int* p, int n) {
    int i = blockIdx.x * blockDim.x + threadIdx.x;
    if (i < n) p[i] = 0;
}

// ---------------- histogram dst; atomic return value = rank within bucket ----------------
__global__ void k_hist(const void* ei, int e, int n,
                       int* __restrict__ cnt, int* __restrict__ rank) {
    int i = blockIdx.x * blockDim.x + threadIdx.x;
    if (i >= e) return;
    int d = g_is64 ? (int)((const long long*)ei)[(size_t)e + i]
                   : ((const int*)ei)[e + i];
    if ((unsigned)d < (unsigned)n) rank[i] = atomicAdd(&cnt[d], 1);
}

// ---------------- 3-phase parallel scan over cnt ----------------
__global__ void __launch_bounds__(SCAN_CHUNK) k_scan1(const int* __restrict__ cnt,
                                                      int* __restrict__ rowstart,
                                                      int* __restrict__ blocksum,
                                                      float* __restrict__ dis, int n) {
    __shared__ int sh[SCAN_CHUNK];
    int t = threadIdx.x;
    int i = blockIdx.x * SCAN_CHUNK + t;
    int v = (i < n) ? cnt[i] : 0;
    if (i < n) dis[i] = rsqrtf((float)v + 1.0f);
    sh[t] = v;
    __syncthreads();
    #pragma unroll
    for (int off = 1; off < SCAN_CHUNK; off <<= 1) {
        int add = (t >= off) ? sh[t - off] : 0;
        __syncthreads();
        sh[t] += add;
        __syncthreads();
    }
    if (i < n) rowstart[i] = sh[t] - v;
    if (t == SCAN_CHUNK - 1) blocksum[blockIdx.x] = sh[SCAN_CHUNK - 1];
}

__global__ void k_scan2(const int* __restrict__ blocksum, int* __restrict__ blockoff,
                        int nb, int* __restrict__ rowstart, int n) {
    __shared__ int sh[MAX_SCAN_BLOCKS];
    int t = threadIdx.x;
    int v = (t < nb) ? blocksum[t] : 0;
    sh[t] = v;
    __syncthreads();
    #pragma unroll
    for (int off = 1; off < MAX_SCAN_BLOCKS; off <<= 1) {
        int add = (t >= off) ? sh[t - off] : 0;
        __syncthreads();
        sh[t] += add;
        __syncthreads();
    }
    if (t < nb) blockoff[t] = sh[t] - v;
    if (t == MAX_SCAN_BLOCKS - 1) rowstart[n] = sh[MAX_SCAN_BLOCKS - 1];
}

__global__ void __launch_bounds__(SCAN_CHUNK) k_scan3(int* __restrict__ rowstart,
                                                      const int* __restrict__ blockoff, int n) {
    int i = blockIdx.x * SCAN_CHUNK + threadIdx.x;
    if (i < n) rowstart[i] += blockoff[blockIdx.x];
}

// ---------------- CSR fill: atomic-free via precomputed rank ----------------
__global__ void k_fill(const void* ei, int e, int n, const float* __restrict__ dis,
                       const int* __restrict__ rowstart, const int* __restrict__ rank,
                       int2* __restrict__ epack) {
    int i = blockIdx.x * blockDim.x + threadIdx.x;
    if (i >= e) return;
    int s, d;
    if (g_is64) {
        const long long* p = (const long long*)ei;
        s = (int)p[i];
        d = (int)p[(size_t)e + i];
    } else {
        const int* p = (const int*)ei;
        s = p[i];
        d = p[e + i];
    }
    if ((unsigned)s >= (unsigned)n || (unsigned)d >= (unsigned)n) return;
    float w = dis[s] * dis[d];
    int p = rowstart[d] + rank[i];
    epack[p] = make_int2(s, __float_as_int(w));
}

// ---------------- tf32 helpers ----------------
__device__ __forceinline__ float to_tf32(float x) {
    unsigned r;
    asm("cvt.rna.tf32.f32 %0, %1;" : "=r"(r) : "f"(x));
    return __uint_as_float(r);
}

__device__ __forceinline__ void mma_tf32(float* c, unsigned a0, unsigned a1,
                                         unsigned a2, unsigned a3,
                                         unsigned b0, unsigned b1) {
    asm volatile(
        "mma.sync.aligned.m16n8k8.row.col.f32.tf32.tf32.f32 "
        "{%0,%1,%2,%3}, {%4,%5,%6,%7}, {%8,%9}, {%0,%1,%2,%3};"
        : "+f"(c[0]), "+f"(c[1]), "+f"(c[2]), "+f"(c[3])
        : "r"(a0), "r"(a1), "r"(a2), "r"(a3), "r"(b0), "r"(b1));
}

// ---------------- GEMM (tf32 tensor core): Yh[n,64] = act(X)[n,64] @ W[64,64] ----------------
__global__ void __launch_bounds__(128) k_gemm_tc(const float* __restrict__ X,
                                                 const float* __restrict__ W,
                                                 __half* __restrict__ Y, int n, int relu_in) {
    __shared__ float sA[GROWS * 68];
    __shared__ float sB[64 * 68];

    int t    = threadIdx.x;
    int row0 = blockIdx.x * GROWS;

    #pragma unroll
    for (int i = 0; i < 8; i++) {
        int idx = i * 512 + t * 4;
        float4 v = *(const float4*)&W[idx];
        int k  = idx >> 6;
        int nn = idx & 63;
        sB[k * 68 + nn + 0] = to_tf32(v.x);
        sB[k * 68 + nn + 1] = to_tf32(v.y);
        sB[k * 68 + nn + 2] = to_tf32(v.z);
        sB[k * 68 + nn + 3] = to_tf32(v.w);
    }
    {
        int kc = (t & 15) * 4;
        int rl = t >> 4;
        #pragma unroll
        for (int i = 0; i < 8; i++) {
            int r  = rl + i * 8;
            int gr = row0 + r;
            float4 v = make_float4(0.f, 0.f, 0.f, 0.f);
            if (gr < n) v = *(const float4*)&X[(size_t)gr * HD + kc];
            if (relu_in) {
                v.x = fmaxf(v.x, 0.f); v.y = fmaxf(v.y, 0.f);
                v.z = fmaxf(v.z, 0.f); v.w = fmaxf(v.w, 0.f);
            }
            sA[r * 68 + kc + 0] = to_tf32(v.x);
            sA[r * 68 + kc + 1] = to_tf32(v.y);
            sA[r * 68 + kc + 2] = to_tf32(v.z);
            sA[r * 68 + kc + 3] = to_tf32(v.w);
        }
    }
    __syncthreads();

    int warp = t >> 5, lane = t & 31;
    int g  = lane >> 2;
    int tq = lane & 3;
    int mrow = warp * 16;

    float c[8][4];
    #pragma unroll
    for (int nf = 0; nf < 8; nf++)
        #pragma unroll
        for (int j = 0; j < 4; j++) c[nf][j] = 0.f;

    #pragma unroll
    for (int kk = 0; kk < 8; kk++) {
        int k0 = kk * 8;
        unsigned a0 = __float_as_uint(sA[(mrow + g)     * 68 + k0 + tq]);
        unsigned a1 = __float_as_uint(sA[(mrow + g + 8) * 68 + k0 + tq]);
        unsigned a2 = __float_as_uint(sA[(mrow + g)     * 68 + k0 + tq + 4]);
        unsigned a3 = __float_as_uint(sA[(mrow + g + 8) * 68 + k0 + tq + 4]);
        #pragma unroll
        for (int nf = 0; nf < 8; nf++) {
            unsigned b0 = __float_as_uint(sB[(k0 + tq)     * 68 + nf * 8 + g]);
            unsigned b1 = __float_as_uint(sB[(k0 + tq + 4) * 68 + nf * 8 + g]);
            mma_tf32(c[nf], a0, a1, a2, a3, b0, b1);
        }
    }

    int gr0 = row0 + mrow + g;
    int gr1 = gr0 + 8;
    #pragma unroll
    for (int nf = 0; nf < 8; nf++) {
        int colb = nf * 8 + 2 * tq;
        if (gr0 < n) {
            __half2 h = __floats2half2_rn(c[nf][0], c[nf][1]);
            *(__half2*)&Y[(size_t)gr0 * HD + colb] = h;
        }
        if (gr1 < n) {
            __half2 h = __floats2half2_rn(c[nf][2], c[nf][3]);
            *(__half2*)&Y[(size_t)gr1 * HD + colb] = h;
        }
    }
}

// ---------------- Gather: one warp per node, HALF-WARP per edge (R9 layout, epack) ----------
// Y[i] = sum_{e in CSR(i)} A[src_e]*w_e  +  A[i]*dis[i]^2  +  b   (fp32 accumulate)
__global__ void __launch_bounds__(256) k_gather(const __half* __restrict__ A,
                                                const int* __restrict__ rowstart,
                                                const int2* __restrict__ epack,
                                                const float* __restrict__ dis,
                                                const float* __restrict__ bias,
                                                float* __restrict__ Y, int n) {
    int wid  = (blockIdx.x * blockDim.x + threadIdx.x) >> 5;
    int lane = threadIdx.x & 31;
    if (wid >= n) return;

    int half_id = lane >> 4;        // 0 or 1: which edge of the pair
    int col     = (lane & 15) * 4;  // 4 fp16 channels per lane (8 bytes)

    float4 acc = make_float4(0.f, 0.f, 0.f, 0.f);

    // Self-loop term (added by half 0 only; shfl-reduce sums halves).
    if (half_id == 0) {
        float d  = dis[wid];
        float sn = d * d;
        uint2 raw = *(const uint2*)&A[(size_t)wid * HD + col];
        float2 f0 = __half22float2(*(__half2*)&raw.x);
        float2 f1 = __half22float2(*(__half2*)&raw.y);
        acc.x = f0.x * sn; acc.y = f0.y * sn;
        acc.z = f1.x * sn; acc.w = f1.y * sn;
    }

    int e0 = rowstart[wid];
    int e1 = rowstart[wid + 1];

    // Each half-warp processes alternating edges: two 128B rows in flight per warp.
    for (int e = e0 + half_id; e < e1; e += 2) {
        int2  p = epack[e];
        float w = __int_as_float(p.y);
        uint2 raw = *(const uint2*)&A[(size_t)p.x * HD + col];
        float2 f0 = __half22float2(*(__half2*)&raw.x);
        float2 f1 = __half22float2(*(__half2*)&raw.y);
        acc.x = fmaf(f0.x, w, acc.x);
        acc.y = fmaf(f0.y, w, acc.y);
        acc.z = fmaf(f1.x, w, acc.z);
        acc.w = fmaf(f1.y, w, acc.w);
    }

    // Combine the two halves.
    acc.x += __shfl_xor_sync(0xffffffffu, acc.x, 16);
    acc.y += __shfl_xor_sync(0xffffffffu, acc.y, 16);
    acc.z += __shfl_xor_sync(0xffffffffu, acc.z, 16);
    acc.w += __shfl_xor_sync(0xffffffffu, acc.w, 16);

    if (half_id == 0) {
        float4 b = *(const float4*)&bias[col];
        acc.x += b.x; acc.y += b.y; acc.z += b.z; acc.w += b.w;
        *(float4*)&Y[(size_t)wid * HD + col] = acc;
    }
}

// ---------------- launch ----------------
extern "C" void kernel_launch(void* const* d_in, const int* in_sizes, int n_in,
                              void* d_out, int out_size) {
    const float* x  = (const float*)d_in[0];
    const void*  ei = d_in[1];   // [2,E]; dtype sniffed on device (int32 vs int64)
    const float* W1 = (const float*)d_in[3];
    const float* b1 = (const float*)d_in[4];
    const float* W2 = (const float*)d_in[5];
    const float* b2 = (const float*)d_in[6];
    const float* W3 = (const float*)d_in[7];
    const float* b3 = (const float*)d_in[8];

    int n = in_sizes[0] / HD;   // 100000
    int e = in_sizes[1] / 2;    // 1600000

    int*    cnt;      cudaGetSymbolAddress((void**)&cnt, g_cnt);
    int*    rowstart; cudaGetSymbolAddress((void**)&rowstart, g_rowstart);
    int*    rank;     cudaGetSymbolAddress((void**)&rank, g_rank);
    float*  dis;      cudaGetSymbolAddress((void**)&dis, g_dis);
    int*    blocksum; cudaGetSymbolAddress((void**)&blocksum, g_blocksum);
    int*    blockoff; cudaGetSymbolAddress((void**)&blockoff, g_blockoff);
    int2*   epack;    cudaGetSymbolAddress((void**)&epack, g_epack);
    __half* bufAh;    cudaGetSymbolAddress((void**)&bufAh, g_bufAh);
    float*  bufB;     cudaGetSymbolAddress((void**)&bufB, g_bufB);
    float*  out = (float*)d_out;

    int nb_n = (n + 255) / 256;
    int nb_e = (e + 255) / 256;
    int nb_g = (n * 32 + 255) / 256;               // one warp per node
    int nb_m = (n + GROWS - 1) / GROWS;            // 64-row GEMM tiles
    int nb_s = (n + SCAN_CHUNK - 1) / SCAN_CHUNK;  // 98 scan blocks

    // ---- CSR build from edge_index (once per call) ----
    k_detect<<<1, 256>>>(ei);
    k_zero_int<<<nb_n, 256>>>(cnt, n);
    k_hist<<<nb_e, 256>>>(ei, e, n, cnt, rank);
    k_scan1<<<nb_s, SCAN_CHUNK>>>(cnt, rowstart, blocksum, dis, n);
    k_scan2<<<1, MAX_SCAN_BLOCKS>>>(blocksum, blockoff, nb_s, rowstart, n);
    k_scan3<<<nb_s, SCAN_CHUNK>>>(rowstart, blockoff, n);
    k_fill<<<nb_e, 256>>>(ei, e, n, dis, rowstart, rank, epack);

    // ---- layer 1 ----
    k_gemm_tc<<<nb_m, 128>>>(x, W1, bufAh, n, 0);
    k_gather<<<nb_g, 256>>>(bufAh, rowstart, epack, dis, b1, bufB, n);
    // ---- layer 2 (ReLU fused into GEMM input load) ----
    k_gemm_tc<<<nb_m, 128>>>(bufB, W2, bufAh, n, 1);
    k_gather<<<nb_g, 256>>>(bufAh, rowstart, epack, dis, b2, bufB, n);
    // ---- layer 3 ----
    k_gemm_tc<<<nb_m, 128>>>(bufB, W3, bufAh, n, 1);
    k_gather<<<nb_g, 256>>>(bufAh, rowstart, epack, dis, b3, out, n);
}

// round 15
// speedup vs baseline: 2.0450x; 1.1002x over previous
#include <cuda_runtime.h>
#include <cuda_fp16.h>
#include <cstdint>

// Problem constants (shapes are fixed by the dataset).
#define NN 100000
#define EE 1600000
#define HD 64
#define SCAN_CHUNK 1024
#define MAX_SCAN_BLOCKS 128
#define GROWS 64    // GEMM rows per block

// ---------------- scratch (device globals: allocation-free) ----------------
__device__ int    g_is64;
__device__ int    g_cnt[NN];
__device__ int    g_rowstart[NN + 1];
__device__ int    g_rank[EE];                               // edge rank within dst bucket
__device__ float  g_dis[NN];
__device__ int    g_blocksum[MAX_SCAN_BLOCKS];
__device__ int    g_blockoff[MAX_SCAN_BLOCKS];
__device__ __align__(128) int    g_csrc[EE];                // CSR src indices (no weights!)
__device__ __align__(128) __half g_bufAh[(size_t)NN * HD];  // fp16 dis_s*h_s (gather in)
__device__ __align__(128) float  g_bufB[(size_t)NN * HD];   // fp32 gather out (GEMM in)

// ---------------- zero cnt + dtype sniff (block 0) in one kernel ----------------
__global__ void k_zerodetect(const void* ei, int* __restrict__ cnt, int n) {
    int i = blockIdx.x * blockDim.x + threadIdx.x;
    if (i < n) cnt[i] = 0;
    if (blockIdx.x == 0) {
        __shared__ int nz;
        if (threadIdx.x == 0) nz = 0;
        __syncthreads();
        // int64 edge_index (values < 2^31) has all-zero odd 32-bit words.
        unsigned v = ((const unsigned*)ei)[2 * threadIdx.x + 1];
        if (v != 0) atomicOr(&nz, 1);
        __syncthreads();
        if (threadIdx.x == 0) g_is64 = (nz == 0) ? 1 : 0;
    }
}

// ---------------- histogram dst; atomic return value = rank within bucket ----------------
__global__ void k_hist(const void* ei, int e, int n,
                       int* __restrict__ cnt, int* __restrict__ rank) {
    int i = blockIdx.x * blockDim.x + threadIdx.x;
    if (i >= e) return;
    int d = g_is64 ? (int)((const long long*)ei)[(size_t)e + i]
                   : ((const int*)ei)[e + i];
    if ((unsigned)d < (unsigned)n) rank[i] = atomicAdd(&cnt[d], 1);
}

// ---------------- 3-phase parallel scan over cnt ----------------
__global__ void __launch_bounds__(SCAN_CHUNK) k_scan1(const int* __restrict__ cnt,
                                                      int* __restrict__ rowstart,
                                                      int* __restrict__ blocksum,
                                                      float* __restrict__ dis, int n) {
    __shared__ int sh[SCAN_CHUNK];
    int t = threadIdx.x;
    int i = blockIdx.x * SCAN_CHUNK + t;
    int v = (i < n) ? cnt[i] : 0;
    if (i < n) dis[i] = rsqrtf((float)v + 1.0f);
    sh[t] = v;
    __syncthreads();
    #pragma unroll
    for (int off = 1; off < SCAN_CHUNK; off <<= 1) {
        int add = (t >= off) ? sh[t - off] : 0;
        __syncthreads();
        sh[t] += add;
        __syncthreads();
    }
    if (i < n) rowstart[i] = sh[t] - v;
    if (t == SCAN_CHUNK - 1) blocksum[blockIdx.x] = sh[SCAN_CHUNK - 1];
}

__global__ void k_scan2(const int* __restrict__ blocksum, int* __restrict__ blockoff,
                        int nb, int* __restrict__ rowstart, int n) {
    __shared__ int sh[MAX_SCAN_BLOCKS];
    int t = threadIdx.x;
    int v = (t < nb) ? blocksum[t] : 0;
    sh[t] = v;
    __syncthreads();
    #pragma unroll
    for (int off = 1; off < MAX_SCAN_BLOCKS; off <<= 1) {
        int add = (t >= off) ? sh[t - off] : 0;
        __syncthreads();
        sh[t] += add;
        __syncthreads();
    }
    if (t < nb) blockoff[t] = sh[t] - v;
    if (t == MAX_SCAN_BLOCKS - 1) rowstart[n] = sh[MAX_SCAN_BLOCKS - 1];
}

__global__ void __launch_bounds__(SCAN_CHUNK) k_scan3(int* __restrict__ rowstart,
                                                      const int* __restrict__ blockoff, int n) {
    int i = blockIdx.x * SCAN_CHUNK + threadIdx.x;
    if (i < n) rowstart[i] += blockoff[blockIdx.x];
}

// ---------------- CSR fill: atomic-free via precomputed rank; 4B payload ----------------
__global__ void k_fill(const void* ei, int e, int n,
                       const int* __restrict__ rowstart, const int* __restrict__ rank,
                       int* __restrict__ csrc) {
    int i = blockIdx.x * blockDim.x + threadIdx.x;
    if (i >= e) return;
    int s, d;
    if (g_is64) {
        const long long* p = (const long long*)ei;
        s = (int)p[i];
        d = (int)p[(size_t)e + i];
    } else {
        const int* p = (const int*)ei;
        s = p[i];
        d = p[e + i];
    }
    if ((unsigned)s >= (unsigned)n || (unsigned)d >= (unsigned)n) return;
    csrc[rowstart[d] + rank[i]] = s;
}

// ---------------- tf32 helpers ----------------
__device__ __forceinline__ float to_tf32(float x) {
    unsigned r;
    asm("cvt.rna.tf32.f32 %0, %1;" : "=r"(r) : "f"(x));
    return __uint_as_float(r);
}

__device__ __forceinline__ void mma_tf32(float* c, unsigned a0, unsigned a1,
                                         unsigned a2, unsigned a3,
                                         unsigned b0, unsigned b1) {
    asm volatile(
        "mma.sync.aligned.m16n8k8.row.col.f32.tf32.tf32.f32 "
        "{%0,%1,%2,%3}, {%4,%5,%6,%7}, {%8,%9}, {%0,%1,%2,%3};"
        : "+f"(c[0]), "+f"(c[1]), "+f"(c[2]), "+f"(c[3])
        : "r"(a0), "r"(a1), "r"(a2), "r"(a3), "r"(b0), "r"(b1));
}

// ---------------- GEMM (tf32 TC): Yh[r,:] = dis[r] * (act(X) @ W)[r,:]  (fp16 out) --------
__global__ void __launch_bounds__(128) k_gemm_tc(const float* __restrict__ X,
                                                 const float* __restrict__ W,
                                                 const float* __restrict__ dis,
                                                 __half* __restrict__ Y, int n, int relu_in) {
    __shared__ float sA[GROWS * 68];
    __shared__ float sB[64 * 68];

    int t    = threadIdx.x;
    int row0 = blockIdx.x * GROWS;

    #pragma unroll
    for (int i = 0; i < 8; i++) {
        int idx = i * 512 + t * 4;
        float4 v = *(const float4*)&W[idx];
        int k  = idx >> 6;
        int nn = idx & 63;
        sB[k * 68 + nn + 0] = to_tf32(v.x);
        sB[k * 68 + nn + 1] = to_tf32(v.y);
        sB[k * 68 + nn + 2] = to_tf32(v.z);
        sB[k * 68 + nn + 3] = to_tf32(v.w);
    }
    {
        int kc = (t & 15) * 4;
        int rl = t >> 4;
        #pragma unroll
        for (int i = 0; i < 8; i++) {
            int r  = rl + i * 8;
            int gr = row0 + r;
            float4 v = make_float4(0.f, 0.f, 0.f, 0.f);
            if (gr < n) v = *(const float4*)&X[(size_t)gr * HD + kc];
            if (relu_in) {
                v.x = fmaxf(v.x, 0.f); v.y = fmaxf(v.y, 0.f);
                v.z = fmaxf(v.z, 0.f); v.w = fmaxf(v.w, 0.f);
            }
            sA[r * 68 + kc + 0] = to_tf32(v.x);
            sA[r * 68 + kc + 1] = to_tf32(v.y);
            sA[r * 68 + kc + 2] = to_tf32(v.z);
            sA[r * 68 + kc + 3] = to_tf32(v.w);
        }
    }
    __syncthreads();

    int warp = t >> 5, lane = t & 31;
    int g  = lane >> 2;
    int tq = lane & 3;
    int mrow = warp * 16;

    float c[8][4];
    #pragma unroll
    for (int nf = 0; nf < 8; nf++)
        #pragma unroll
        for (int j = 0; j < 4; j++) c[nf][j] = 0.f;

    #pragma unroll
    for (int kk = 0; kk < 8; kk++) {
        int k0 = kk * 8;
        unsigned a0 = __float_as_uint(sA[(mrow + g)     * 68 + k0 + tq]);
        unsigned a1 = __float_as_uint(sA[(mrow + g + 8) * 68 + k0 + tq]);
        unsigned a2 = __float_as_uint(sA[(mrow + g)     * 68 + k0 + tq + 4]);
        unsigned a3 = __float_as_uint(sA[(mrow + g + 8) * 68 + k0 + tq + 4]);
        #pragma unroll
        for (int nf = 0; nf < 8; nf++) {
            unsigned b0 = __float_as_uint(sB[(k0 + tq)     * 68 + nf * 8 + g]);
            unsigned b1 = __float_as_uint(sB[(k0 + tq + 4) * 68 + nf * 8 + g]);
            mma_tf32(c[nf], a0, a1, a2, a3, b0, b1);
        }
    }

    int gr0 = row0 + mrow + g;
    int gr1 = gr0 + 8;
    float d0 = (gr0 < n) ? dis[gr0] : 0.f;   // fold dis_s into stored features
    float d1 = (gr1 < n) ? dis[gr1] : 0.f;
    #pragma unroll
    for (int nf = 0; nf < 8; nf++) {
        int colb = nf * 8 + 2 * tq;
        if (gr0 < n) {
            __half2 h = __floats2half2_rn(c[nf][0] * d0, c[nf][1] * d0);
            *(__half2*)&Y[(size_t)gr0 * HD + colb] = h;
        }
        if (gr1 < n) {
            __half2 h = __floats2half2_rn(c[nf][2] * d1, c[nf][3] * d1);
            *(__half2*)&Y[(size_t)gr1 * HD + colb] = h;
        }
    }
}

// ---------------- Gather: warp per node, half-warp per edge, WEIGHT-FREE rows -------------
// A holds A'[s] = dis_s * h_s.   Y[i] = dis_i * ( sum_e A'[src_e] + A'[i] ) + b
__global__ void __launch_bounds__(256) k_gather(const __half* __restrict__ A,
                                                const int* __restrict__ rowstart,
                                                const int* __restrict__ csrc,
                                                const float* __restrict__ dis,
                                                const float* __restrict__ bias,
                                                float* __restrict__ Y, int n) {
    int wid  = (blockIdx.x * blockDim.x + threadIdx.x) >> 5;
    int lane = threadIdx.x & 31;
    if (wid >= n) return;

    int half_id = lane >> 4;        // 0 or 1: which edge of the pair
    int col     = (lane & 15) * 4;  // 4 fp16 channels per lane (8 bytes)

    float4 acc = make_float4(0.f, 0.f, 0.f, 0.f);

    // Self-loop term: add A'[i] (half 0 only; shfl-reduce folds it in).
    if (half_id == 0) {
        uint2 raw = *(const uint2*)&A[(size_t)wid * HD + col];
        float2 f0 = __half22float2(*(__half2*)&raw.x);
        float2 f1 = __half22float2(*(__half2*)&raw.y);
        acc.x = f0.x; acc.y = f0.y;
        acc.z = f1.x; acc.w = f1.y;
    }

    int e0 = rowstart[wid];
    int e1 = rowstart[wid + 1];

    // Each half-warp processes alternating edges: two 128B rows in flight per warp.
    for (int e = e0 + half_id; e < e1; e += 2) {
        int s = csrc[e];            // warp-uniform-per-half broadcast load
        uint2 raw = *(const uint2*)&A[(size_t)s * HD + col];
        float2 f0 = __half22float2(*(__half2*)&raw.x);
        float2 f1 = __half22float2(*(__half2*)&raw.y);
        acc.x += f0.x; acc.y += f0.y;
        acc.z += f1.x; acc.w += f1.y;
    }

    // Combine the two halves.
    acc.x += __shfl_xor_sync(0xffffffffu, acc.x, 16);
    acc.y += __shfl_xor_sync(0xffffffffu, acc.y, 16);
    acc.z += __shfl_xor_sync(0xffffffffu, acc.z, 16);
    acc.w += __shfl_xor_sync(0xffffffffu, acc.w, 16);

    if (half_id == 0) {
        float  di = dis[wid];
        float4 b  = *(const float4*)&bias[col];
        acc.x = fmaf(acc.x, di, b.x);
        acc.y = fmaf(acc.y, di, b.y);
        acc.z = fmaf(acc.z, di, b.z);
        acc.w = fmaf(acc.w, di, b.w);
        *(float4*)&Y[(size_t)wid * HD + col] = acc;
    }
}

// ---------------- launch ----------------
extern "C" void kernel_launch(void* const* d_in, const int* in_sizes, int n_in,
                              void* d_out, int out_size) {
    const float* x  = (const float*)d_in[0];
    const void*  ei = d_in[1];   // [2,E]; dtype sniffed on device (int32 vs int64)
    const float* W1 = (const float*)d_in[3];
    const float* b1 = (const float*)d_in[4];
    const float* W2 = (const float*)d_in[5];
    const float* b2 = (const float*)d_in[6];
    const float* W3 = (const float*)d_in[7];
    const float* b3 = (const float*)d_in[8];

    int n = in_sizes[0] / HD;   // 100000
    int e = in_sizes[1] / 2;    // 1600000

    int*    cnt;      cudaGetSymbolAddress((void**)&cnt, g_cnt);
    int*    rowstart; cudaGetSymbolAddress((void**)&rowstart, g_rowstart);
    int*    rank;     cudaGetSymbolAddress((void**)&rank, g_rank);
    float*  dis;      cudaGetSymbolAddress((void**)&dis, g_dis);
    int*    blocksum; cudaGetSymbolAddress((void**)&blocksum, g_blocksum);
    int*    blockoff; cudaGetSymbolAddress((void**)&blockoff, g_blockoff);
    int*    csrc;     cudaGetSymbolAddress((void**)&csrc, g_csrc);
    __half* bufAh;    cudaGetSymbolAddress((void**)&bufAh, g_bufAh);
    float*  bufB;     cudaGetSymbolAddress((void**)&bufB, g_bufB);
    float*  out = (float*)d_out;

    int nb_n = (n + 255) / 256;
    int nb_e = (e + 255) / 256;
    int nb_g = (n * 32 + 255) / 256;               // one warp per node
    int nb_m = (n + GROWS - 1) / GROWS;            // 64-row GEMM tiles
    int nb_s = (n + SCAN_CHUNK - 1) / SCAN_CHUNK;  // 98 scan blocks

    // ---- CSR build from edge_index (once per call) ----
    k_zerodetect<<<nb_n, 256>>>(ei, cnt, n);
    k_hist<<<nb_e, 256>>>(ei, e, n, cnt, rank);
    k_scan1<<<nb_s, SCAN_CHUNK>>>(cnt, rowstart, blocksum, dis, n);
    k_scan2<<<1, MAX_SCAN_BLOCKS>>>(blocksum, blockoff, nb_s, rowstart, n);
    k_scan3<<<nb_s, SCAN_CHUNK>>>(rowstart, blockoff, n);
    k_fill<<<nb_e, 256>>>(ei, e, n, rowstart, rank, csrc);

    // ---- layer 1 ----
    k_gemm_tc<<<nb_m, 128>>>(x, W1, dis, bufAh, n, 0);
    k_gather<<<nb_g, 256>>>(bufAh, rowstart, csrc, dis, b1, bufB, n);
    // ---- layer 2 (ReLU fused into GEMM input load) ----
    k_gemm_tc<<<nb_m, 128>>>(bufB, W2, dis, bufAh, n, 1);
    k_gather<<<nb_g, 256>>>(bufAh, rowstart, csrc, dis, b2, bufB, n);
    // ---- layer 3 ----
    k_gemm_tc<<<nb_m, 128>>>(bufB, W3, dis, bufAh, n, 1);
    k_gather<<<nb_g, 256>>>(bufAh, rowstart, csrc, dis, b3, out, n);
}